// round 15
// baseline (speedup 1.0000x reference)
#include <cuda_runtime.h>
#include <cuda_bf16.h>

#define Nn   40000
#define Mm   10000
#define NNZn 400000
#define NGn  128
#define EPSb 1e-5f

// ---------------- device scratch (allocation-free rules) ----------------
__device__ __align__(16) float g_E[Mm * 256];     // E0 [M,128] then E1 [M,256]
__device__ __align__(16) float g_G[Nn * 128];     // G0 [N,128]
__device__ __align__(16) float g_LIN[Nn * 256];   // LIN0 then LIN1
__device__ __align__(16) float g_H0[Nn * 256];
__device__ __align__(16) float g_H1[Nn * 256];
__device__ __align__(16) float g_F[Mm * 256];     // E1 @ W1_1
__device__ __align__(16) float g_z[Nn * 16];
__device__ __align__(16) float g_Ez[Mm * 16];
__device__ __align__(16) float g_Gz[Nn * 16];
__device__ float g_dinv[Nn];
__device__ int   g_cntE[Mm];
__device__ int   g_cntN[Nn];
__device__ int   g_rpE[Mm + 1];
__device__ int   g_rpN[Nn + 1];
__device__ int   g_curE[Mm];
__device__ int   g_curN[Nn];
__device__ int   g_colE[NNZn];
__device__ int   g_colN[NNZn];
__device__ int   g_part[64];       // scan partials: [0..15] E, [16..63] N
__device__ float g_stats[512];     // [sum 256 | sumsq 256]
__device__ __align__(16) float g_bn_s[4][256];
__device__ __align__(16) float g_bn_t[4][256];

__device__ __forceinline__ float4 bnrelu4(float4 v, float4 s, float4 t) {
    v.x = fmaxf(fmaf(v.x, s.x, t.x), 0.f);
    v.y = fmaxf(fmaf(v.y, s.y, t.y), 0.f);
    v.z = fmaxf(fmaf(v.z, s.z, t.z), 0.f);
    v.w = fmaxf(fmaf(v.w, s.w, t.w), 0.f);
    return v;
}

// pack two floats into bf16x2 hi and residual-lo words (x in low half)
__device__ __forceinline__ void split2(float x, float y, unsigned& hi, unsigned& lo) {
    __nv_bfloat16 hx = __float2bfloat16_rn(x), hy = __float2bfloat16_rn(y);
    __nv_bfloat16 lx = __float2bfloat16_rn(x - __bfloat162float(hx));
    __nv_bfloat16 ly = __float2bfloat16_rn(y - __bfloat162float(hy));
    __nv_bfloat162 h2(hx, hy), l2(lx, ly);
    hi = *(unsigned*)&h2;
    lo = *(unsigned*)&l2;
}

__device__ __forceinline__ void mma_bf16(float* c, const unsigned* a, const unsigned* b) {
    asm volatile("mma.sync.aligned.m16n8k16.row.col.f32.bf16.bf16.f32 "
                 "{%0,%1,%2,%3}, {%4,%5,%6,%7}, {%8,%9}, {%0,%1,%2,%3};"
                 : "+f"(c[0]), "+f"(c[1]), "+f"(c[2]), "+f"(c[3])
                 : "r"(a[0]), "r"(a[1]), "r"(a[2]), "r"(a[3]),
                   "r"(b[0]), "r"(b[1]));
}

// ---------------- prep ----------------
__global__ void hg_prep() {
    int i = blockIdx.x * blockDim.x + threadIdx.x;
    if (i < Mm)  g_cntE[i] = 0;
    if (i < Nn)  g_cntN[i] = 0;
    if (i < 512) g_stats[i] = 0.f;
}

__global__ void hg_count(const int* __restrict__ ei, const int* __restrict__ ni) {
    int k = blockIdx.x * blockDim.x + threadIdx.x;
    if (k >= NNZn) return;
    atomicAdd(&g_cntE[ei[k]], 1);
    atomicAdd(&g_cntN[ni[k]], 1);
}

// ---------------- multi-block two-level scan ----------------
__global__ void hg_scan1(const int* __restrict__ cnt, int* __restrict__ rp, int n, int pbase) {
    __shared__ int wsum[32];
    int i = blockIdx.x * 1024 + threadIdx.x;
    int lane = threadIdx.x & 31, wid = threadIdx.x >> 5;
    int v = (i < n) ? cnt[i] : 0;
    int x = v;
    #pragma unroll
    for (int d = 1; d < 32; d <<= 1) {
        int t = __shfl_up_sync(0xffffffffu, x, d);
        if (lane >= d) x += t;
    }
    if (lane == 31) wsum[wid] = x;
    __syncthreads();
    if (wid == 0) {
        int w = wsum[lane];
        #pragma unroll
        for (int d = 1; d < 32; d <<= 1) {
            int t = __shfl_up_sync(0xffffffffu, w, d);
            if (lane >= d) w += t;
        }
        wsum[lane] = w;
    }
    __syncthreads();
    int excl = x - v + (wid > 0 ? wsum[wid - 1] : 0);
    if (i < n) rp[i] = excl;
    if (threadIdx.x == 1023) g_part[pbase + blockIdx.x] = excl + v;
}

__global__ void hg_scan2(int nbE, int nbN) {
    if (threadIdx.x == 0) {
        int s = 0;
        for (int i = 0; i < nbE; i++) { int t = g_part[i]; g_part[i] = s; s += t; }
        g_rpE[Mm] = s;
    }
    if (threadIdx.x == 1) {
        int s = 0;
        for (int i = 16; i < 16 + nbN; i++) { int t = g_part[i]; g_part[i] = s; s += t; }
        g_rpN[Nn] = s;
    }
}

__global__ void hg_scan3(int* __restrict__ rp, int* __restrict__ cur, int n, int pbase) {
    int i = blockIdx.x * 1024 + threadIdx.x;
    if (i >= n) return;
    int v = rp[i] + g_part[pbase + (i >> 10)];
    rp[i] = v;
    cur[i] = v;
}

__global__ void hg_fill(const int* __restrict__ ei, const int* __restrict__ ni) {
    int k = blockIdx.x * blockDim.x + threadIdx.x;
    if (k >= NNZn) return;
    int e = ei[k], nd = ni[k];
    int pe = atomicAdd(&g_curE[e], 1);  g_colE[pe] = nd;
    int pn = atomicAdd(&g_curN[nd], 1); g_colN[pn] = e;
}

__global__ void hg_dinv() {
    int i = blockIdx.x * blockDim.x + threadIdx.x;
    if (i >= Nn) return;
    int s = 0;
    for (int b = g_rpN[i], e = g_rpN[i + 1]; b < e; ++b) s += g_cntE[g_colN[b]];
    g_dinv[i] = (s > 0) ? 1.f / (float)s : 1.f;
}

// ---------------- pull-based segment sum ----------------
template <int NF4>
__global__ void hg_seg_pull(const int* __restrict__ rp, const int* __restrict__ col,
                            const float4* __restrict__ src, float4* __restrict__ dst,
                            int nseg, int slot) {
    const int WPS = NF4 / 32;
    int gw  = (blockIdx.x * blockDim.x + threadIdx.x) >> 5;
    int seg = gw / WPS;
    if (seg >= nseg) return;
    int f4 = (gw % WPS) * 32 + (threadIdx.x & 31);
    float4 sv, tv;
    bool bn = (slot >= 0);
    if (bn) {
        sv = *(const float4*)&g_bn_s[slot][f4 * 4];
        tv = *(const float4*)&g_bn_t[slot][f4 * 4];
    }
    float4 acc = make_float4(0.f, 0.f, 0.f, 0.f);
    int b = rp[seg], e = rp[seg + 1];
    for (; b + 1 < e; b += 2) {
        int r0 = col[b], r1 = col[b + 1];
        float4 v0 = __ldg(&src[(size_t)r0 * NF4 + f4]);
        float4 v1 = __ldg(&src[(size_t)r1 * NF4 + f4]);
        if (bn) { v0 = bnrelu4(v0, sv, tv); v1 = bnrelu4(v1, sv, tv); }
        acc.x += v0.x + v1.x; acc.y += v0.y + v1.y;
        acc.z += v0.z + v1.z; acc.w += v0.w + v1.w;
    }
    if (b < e) {
        float4 v0 = __ldg(&src[(size_t)col[b] * NF4 + f4]);
        if (bn) v0 = bnrelu4(v0, sv, tv);
        acc.x += v0.x; acc.y += v0.y; acc.z += v0.z; acc.w += v0.w;
    }
    dst[(size_t)seg * NF4 + f4] = acc;
}

__global__ void hg_seg_pull16(const int* __restrict__ rp, const int* __restrict__ col,
                              const float* __restrict__ src, float* __restrict__ dst, int nseg) {
    int t = blockIdx.x * blockDim.x + threadIdx.x;
    int seg = t >> 4;
    if (seg >= nseg) return;
    int f = t & 15;
    float acc = 0.f;
    for (int b = rp[seg], e = rp[seg + 1]; b < e; ++b)
        acc += __ldg(&src[(size_t)col[b] * 16 + f]);
    dst[(size_t)seg * 16 + f] = acc;
}

// ---------------- tensor-core GEMM: C = act(A)[Mr,K] @ B[K,Nc] ----------------
// bf16 3-split (hi*hi + hi*lo + lo*hi) -> ~1e-5 rel err, fp32 accumulate.
// Block tile 128x128, 8 warps in 2(M)x4(N), warp tile 64x32 = 4x4 m16n8k16.
// slot>=0: BN+ReLU fused on A load. doStats: column sum/sumsq -> g_stats.
__global__ __launch_bounds__(256) void hg_gemm_tc(
        const float* __restrict__ A, const float* __restrict__ B, float* __restrict__ C,
        int Mr, int K, int Nc, int slot, int doStats) {
    __shared__ unsigned Ah[128][17], Al[128][17];
    __shared__ unsigned Bh[16][136], Bl[16][136];
    __shared__ float s_sum[128], s_sq[128];

    int tid = threadIdx.x;
    int lane = tid & 31, wid = tid >> 5;
    int wm = wid & 1, wn = wid >> 1;
    int row0 = blockIdx.y * 128, col0 = blockIdx.x * 128;

    if (doStats && tid < 128) { s_sum[tid] = 0.f; s_sq[tid] = 0.f; }

    float c[4][4][4];
    #pragma unroll
    for (int mi = 0; mi < 4; mi++)
        #pragma unroll
        for (int ni = 0; ni < 4; ni++)
            #pragma unroll
            for (int q = 0; q < 4; q++) c[mi][ni][q] = 0.f;

    int arow = tid >> 3;          // 0..31
    int acol = (tid & 7) * 4;     // 0..28
    int bk2  = tid >> 4;          // 0..15
    int bnn  = (tid & 15) * 8;    // 0..120

    for (int k0 = 0; k0 < K; k0 += 32) {
        // A tile 128x32 fp32 -> bf16 hi/lo, BN+ReLU fused
        #pragma unroll
        for (int rr = 0; rr < 128; rr += 32) {
            int r = rr + arow;
            int gr = row0 + r;
            float4 v = make_float4(0.f, 0.f, 0.f, 0.f);
            if (gr < Mr) v = __ldg((const float4*)(A + (size_t)gr * K + k0 + acol));
            if (slot >= 0) {
                float4 s4 = *(const float4*)&g_bn_s[slot][k0 + acol];
                float4 t4 = *(const float4*)&g_bn_t[slot][k0 + acol];
                v = bnrelu4(v, s4, t4);
            }
            unsigned h0, l0, h1, l1;
            split2(v.x, v.y, h0, l0);
            split2(v.z, v.w, h1, l1);
            int kc = acol >> 1;
            Ah[r][kc] = h0;  Al[r][kc] = l0;
            Ah[r][kc + 1] = h1;  Al[r][kc + 1] = l1;
        }
        // B tile 32x128: pair along k
        {
            const float* Bp = B + (size_t)(k0 + 2 * bk2) * Nc + col0 + bnn;
            float4 r0a = __ldg((const float4*)Bp);
            float4 r0b = __ldg((const float4*)(Bp + 4));
            float4 r1a = __ldg((const float4*)(Bp + Nc));
            float4 r1b = __ldg((const float4*)(Bp + Nc + 4));
            unsigned h, l;
            split2(r0a.x, r1a.x, h, l); Bh[bk2][bnn + 0] = h; Bl[bk2][bnn + 0] = l;
            split2(r0a.y, r1a.y, h, l); Bh[bk2][bnn + 1] = h; Bl[bk2][bnn + 1] = l;
            split2(r0a.z, r1a.z, h, l); Bh[bk2][bnn + 2] = h; Bl[bk2][bnn + 2] = l;
            split2(r0a.w, r1a.w, h, l); Bh[bk2][bnn + 3] = h; Bl[bk2][bnn + 3] = l;
            split2(r0b.x, r1b.x, h, l); Bh[bk2][bnn + 4] = h; Bl[bk2][bnn + 4] = l;
            split2(r0b.y, r1b.y, h, l); Bh[bk2][bnn + 5] = h; Bl[bk2][bnn + 5] = l;
            split2(r0b.z, r1b.z, h, l); Bh[bk2][bnn + 6] = h; Bl[bk2][bnn + 6] = l;
            split2(r0b.w, r1b.w, h, l); Bh[bk2][bnn + 7] = h; Bl[bk2][bnn + 7] = l;
        }
        __syncthreads();
        #pragma unroll
        for (int s = 0; s < 2; s++) {
            unsigned ah[4][4], al[4][4], bh[4][2], bl[4][2];
            int kp = s * 8 + (lane & 3);
            #pragma unroll
            for (int mi = 0; mi < 4; mi++) {
                int r = wm * 64 + mi * 16 + (lane >> 2);
                ah[mi][0] = Ah[r][kp];     ah[mi][1] = Ah[r + 8][kp];
                ah[mi][2] = Ah[r][kp + 4]; ah[mi][3] = Ah[r + 8][kp + 4];
                al[mi][0] = Al[r][kp];     al[mi][1] = Al[r + 8][kp];
                al[mi][2] = Al[r][kp + 4]; al[mi][3] = Al[r + 8][kp + 4];
            }
            #pragma unroll
            for (int ni = 0; ni < 4; ni++) {
                int n = wn * 32 + ni * 8 + (lane >> 2);
                bh[ni][0] = Bh[kp][n]; bh[ni][1] = Bh[kp + 4][n];
                bl[ni][0] = Bl[kp][n]; bl[ni][1] = Bl[kp + 4][n];
            }
            #pragma unroll
            for (int mi = 0; mi < 4; mi++)
                #pragma unroll
                for (int ni = 0; ni < 4; ni++) {
                    mma_bf16(c[mi][ni], ah[mi], bh[ni]);
                    mma_bf16(c[mi][ni], ah[mi], bl[ni]);
                    mma_bf16(c[mi][ni], al[mi], bh[ni]);
                }
        }
        __syncthreads();
    }

    // store + fused BN stats
    #pragma unroll
    for (int ni = 0; ni < 4; ni++) {
        int lc = wn * 32 + ni * 8 + (lane & 3) * 2;
        float s0 = 0.f, s1 = 0.f, q0 = 0.f, q1 = 0.f;
        #pragma unroll
        for (int mi = 0; mi < 4; mi++) {
            int r = row0 + wm * 64 + mi * 16 + (lane >> 2);
            float* cf = c[mi][ni];
            if (r < Mr) {
                *(float2*)&C[(size_t)r * Nc + col0 + lc] = make_float2(cf[0], cf[1]);
                s0 += cf[0]; q0 = fmaf(cf[0], cf[0], q0);
                s1 += cf[1]; q1 = fmaf(cf[1], cf[1], q1);
            }
            if (r + 8 < Mr) {
                *(float2*)&C[(size_t)(r + 8) * Nc + col0 + lc] = make_float2(cf[2], cf[3]);
                s0 += cf[2]; q0 = fmaf(cf[2], cf[2], q0);
                s1 += cf[3]; q1 = fmaf(cf[3], cf[3], q1);
            }
        }
        if (doStats) {
            atomicAdd(&s_sum[lc], s0);     atomicAdd(&s_sq[lc], q0);
            atomicAdd(&s_sum[lc + 1], s1); atomicAdd(&s_sq[lc + 1], q1);
        }
    }
    if (doStats) {
        __syncthreads();
        if (tid < 128) {
            atomicAdd(&g_stats[col0 + tid], s_sum[tid]);
            atomicAdd(&g_stats[256 + col0 + tid], s_sq[tid]);
        }
    }
}

// ---------------- BatchNorm stats (for pull-produced tensors) ----------------
__global__ void hg_bn_stats(const float* __restrict__ Xm, int R) {
    int f  = threadIdx.x;
    int r0 = blockIdx.x * 128;
    int r1 = min(r0 + 128, R);
    float s = 0.f, s2 = 0.f;
    for (int r = r0; r < r1; ++r) {
        float v = Xm[(size_t)r * 256 + f];
        s += v;
        s2 = fmaf(v, v, s2);
    }
    atomicAdd(&g_stats[f], s);
    atomicAdd(&g_stats[256 + f], s2);
}

__global__ void hg_bn_fin(const float* __restrict__ gamma, const float* __restrict__ beta,
                          int slot, float Rf) {
    int f = threadIdx.x;
    float m  = g_stats[f] / Rf;
    float v  = g_stats[256 + f] / Rf - m * m;
    float sc = gamma[f] * rsqrtf(v + EPSb);
    g_bn_s[slot][f] = sc;
    g_bn_t[slot][f] = beta[f] - m * sc;
    g_stats[f] = 0.f;
    g_stats[256 + f] = 0.f;
}

// ------ head: z = relu(bn1(H0))@Wh0 + relu(bn3(H1))@Wh1, padded to 16 ------
__global__ void hg_head(const float* __restrict__ W) {
    __shared__ float Ws[5120];
    for (int l = threadIdx.x; l < 5120; l += blockDim.x) Ws[l] = W[l];
    __syncthreads();
    int t  = blockIdx.x * blockDim.x + threadIdx.x;
    int r0 = t * 2;
    if (r0 >= Nn) return;
    float acc0[10], acc1[10];
    #pragma unroll
    for (int c = 0; c < 10; c++) { acc0[c] = 0.f; acc1[c] = 0.f; }
    #pragma unroll
    for (int half = 0; half < 2; half++) {
        const float4* Hs = (const float4*)(half ? g_H1 : g_H0);
        const float4* sp = (const float4*)(half ? g_bn_s[3] : g_bn_s[1]);
        const float4* tp = (const float4*)(half ? g_bn_t[3] : g_bn_t[1]);
        const float* Wp = Ws + half * 2560;
        for (int k4 = 0; k4 < 64; k4++) {
            float4 ss = sp[k4], tt = tp[k4];
            float4 x0 = __ldg(&Hs[(size_t)r0 * 64 + k4]);
            float4 x1 = __ldg(&Hs[(size_t)(r0 + 1) * 64 + k4]);
            float a0[4], a1[4];
            *(float4*)a0 = bnrelu4(x0, ss, tt);
            *(float4*)a1 = bnrelu4(x1, ss, tt);
            const float* wr = Wp + k4 * 40;
            #pragma unroll
            for (int kk = 0; kk < 4; kk++)
                #pragma unroll
                for (int c = 0; c < 10; c++) {
                    float w = wr[kk * 10 + c];
                    acc0[c] = fmaf(a0[kk], w, acc0[c]);
                    acc1[c] = fmaf(a1[kk], w, acc1[c]);
                }
        }
    }
    #pragma unroll
    for (int c = 0; c < 10; c++) {
        g_z[(size_t)r0 * 16 + c] = acc0[c];
        g_z[(size_t)(r0 + 1) * 16 + c] = acc1[c];
    }
    #pragma unroll
    for (int c = 10; c < 16; c++) {
        g_z[(size_t)r0 * 16 + c] = 0.f;
        g_z[(size_t)(r0 + 1) * 16 + c] = 0.f;
    }
}

// ---------------- per-graph mean readout ----------------
__global__ void hg_readout(const int* __restrict__ batch, const float* __restrict__ head_b,
                           float* __restrict__ dout) {
    __shared__ int s_lo, s_hi;
    __shared__ float red[256];
    int g = blockIdx.x;
    if (threadIdx.x == 0) {
        int lo = 0, hi = Nn;
        while (lo < hi) { int mid = (lo + hi) >> 1; if (batch[mid] < g) lo = mid + 1; else hi = mid; }
        s_lo = lo;
        lo = 0; hi = Nn;
        while (lo < hi) { int mid = (lo + hi) >> 1; if (batch[mid] < g + 1) lo = mid + 1; else hi = mid; }
        s_hi = lo;
    }
    __syncthreads();
    int lo = s_lo, hi = s_hi;
    float acc[10];
    #pragma unroll
    for (int c = 0; c < 10; c++) acc[c] = 0.f;
    for (int n = lo + (int)threadIdx.x; n < hi; n += 256) {
        float dv = g_dinv[n];
        #pragma unroll
        for (int c = 0; c < 10; c++) acc[c] = fmaf(dv, g_Gz[(size_t)n * 16 + c], acc[c]);
    }
    int cnt = hi - lo;
    for (int c = 0; c < 10; c++) {
        red[threadIdx.x] = acc[c];
        __syncthreads();
        for (int s = 128; s > 0; s >>= 1) {
            if ((int)threadIdx.x < s) red[threadIdx.x] += red[threadIdx.x + s];
            __syncthreads();
        }
        if (threadIdx.x == 0)
            dout[g * 10 + c] = (cnt > 0) ? red[0] / (float)cnt + head_b[c] : 0.f;
        __syncthreads();
    }
}

extern "C" void kernel_launch(void* const* d_in, const int* in_sizes, int n_in,
                              void* d_out, int out_size) {
    const float* X     = (const float*)d_in[0];
    const int*   ni    = (const int*)d_in[1];
    const int*   ei    = (const int*)d_in[2];
    const int*   batch = (const int*)d_in[3];
    const float* W1_0  = (const float*)d_in[4];
    const float* g1_0  = (const float*)d_in[6];
    const float* be1_0 = (const float*)d_in[7];
    const float* W2_0  = (const float*)d_in[8];
    const float* bng_0 = (const float*)d_in[10];
    const float* bnb_0 = (const float*)d_in[11];
    const float* W1_1  = (const float*)d_in[12];
    const float* g1_1  = (const float*)d_in[14];
    const float* be1_1 = (const float*)d_in[15];
    const float* W2_1  = (const float*)d_in[16];
    const float* bng_1 = (const float*)d_in[18];
    const float* bnb_1 = (const float*)d_in[19];
    const float* headW = (const float*)d_in[20];
    const float* headb = (const float*)d_in[21];
    float* dout = (float*)d_out;

    float *pE, *pG, *pLIN, *pH0, *pH1, *pF, *pz, *pEz, *pGz;
    int *pcntE, *pcntN, *prpE, *prpN, *pcurE, *pcurN, *pcolE, *pcolN;
    cudaGetSymbolAddress((void**)&pE,   g_E);
    cudaGetSymbolAddress((void**)&pG,   g_G);
    cudaGetSymbolAddress((void**)&pLIN, g_LIN);
    cudaGetSymbolAddress((void**)&pH0,  g_H0);
    cudaGetSymbolAddress((void**)&pH1,  g_H1);
    cudaGetSymbolAddress((void**)&pF,   g_F);
    cudaGetSymbolAddress((void**)&pz,   g_z);
    cudaGetSymbolAddress((void**)&pEz,  g_Ez);
    cudaGetSymbolAddress((void**)&pGz,  g_Gz);
    cudaGetSymbolAddress((void**)&pcntE, g_cntE);
    cudaGetSymbolAddress((void**)&pcntN, g_cntN);
    cudaGetSymbolAddress((void**)&prpE,  g_rpE);
    cudaGetSymbolAddress((void**)&prpN,  g_rpN);
    cudaGetSymbolAddress((void**)&pcurE, g_curE);
    cudaGetSymbolAddress((void**)&pcurN, g_curN);
    cudaGetSymbolAddress((void**)&pcolE, g_colE);
    cudaGetSymbolAddress((void**)&pcolN, g_colN);

    const float Rf = (float)Nn;
    const int nbE = (Mm + 1023) / 1024;    // 10
    const int nbN = (Nn + 1023) / 1024;    // 40
    dim3 gN(2, (Nn + 127) / 128);          // TC gemm grids (Nc=256)
    dim3 gM(2, (Mm + 127) / 128);
    int statsG = (Nn + 127) / 128;

    // graph structure (CSR build, atomic-free pulls afterwards)
    hg_prep<<<(Nn + 255) / 256, 256>>>();
    hg_count<<<(NNZn + 255) / 256, 256>>>(ei, ni);
    hg_scan1<<<nbE, 1024>>>(pcntE, prpE, Mm, 0);
    hg_scan1<<<nbN, 1024>>>(pcntN, prpN, Nn, 16);
    hg_scan2<<<1, 32>>>(nbE, nbN);
    hg_scan3<<<nbE, 1024>>>(prpE, pcurE, Mm, 0);
    hg_scan3<<<nbN, 1024>>>(prpN, pcurN, Nn, 16);
    hg_fill<<<(NNZn + 255) / 256, 256>>>(ei, ni);
    hg_dinv<<<(Nn + 255) / 256, 256>>>();

    // layer 0
    hg_seg_pull<32><<<(Mm * 32 + 255) / 256, 256>>>(prpE, pcolE, (const float4*)X, (float4*)pE, Mm, -1);
    hg_seg_pull<32><<<(Nn * 32 + 255) / 256, 256>>>(prpN, pcolN, (const float4*)pE, (float4*)pG, Nn, -1);
    hg_gemm_tc<<<gN, 256>>>(pG, W1_0, pLIN, Nn, 128, 256, -1, 1);
    hg_bn_fin<<<1, 256>>>(g1_0, be1_0, 0, Rf);
    hg_gemm_tc<<<gN, 256>>>(pLIN, W2_0, pH0, Nn, 256, 256, 0, 1);
    hg_bn_fin<<<1, 256>>>(bng_0, bnb_0, 1, Rf);

    // layer 1 (W1_1 folded through H: GEMM at M rows)
    hg_seg_pull<64><<<(Mm * 64 + 255) / 256, 256>>>(prpE, pcolE, (const float4*)pH0, (float4*)pE, Mm, 1);
    hg_gemm_tc<<<gM, 256>>>(pE, W1_1, pF, Mm, 256, 256, -1, 0);
    hg_seg_pull<64><<<(Nn * 64 + 255) / 256, 256>>>(prpN, pcolN, (const float4*)pF, (float4*)pLIN, Nn, -1);
    hg_bn_stats<<<statsG, 256>>>(pLIN, Nn);
    hg_bn_fin<<<1, 256>>>(g1_1, be1_1, 2, Rf);
    hg_gemm_tc<<<gN, 256>>>(pLIN, W2_1, pH1, Nn, 256, 256, 2, 1);
    hg_bn_fin<<<1, 256>>>(bng_1, bnb_1, 3, Rf);

    // head folded before final propagation, then readout
    hg_head<<<(Nn / 2 + 255) / 256, 256>>>(headW);
    hg_seg_pull16<<<(Mm * 16 + 255) / 256, 256>>>(prpE, pcolE, pz, pEz, Mm);
    hg_seg_pull16<<<(Nn * 16 + 255) / 256, 256>>>(prpN, pcolN, pEz, pGz, Nn);
    hg_readout<<<NGn, 256>>>(batch, headb, dout);
}

// round 16
// speedup vs baseline: 1.0138x; 1.0138x over previous
#include <cuda_runtime.h>
#include <cuda_bf16.h>

#define Nn   40000
#define Mm   10000
#define NNZn 400000
#define NGn  128
#define EPSb 1e-5f

// ---------------- device scratch (allocation-free rules) ----------------
__device__ __align__(16) float g_E[Mm * 256];     // E0 [M,128] then E1 [M,256]
__device__ __align__(16) float g_G[Nn * 128];     // G0 [N,128]
__device__ __align__(16) float g_LIN[Nn * 256];   // LIN0 then LIN1
__device__ __align__(16) float g_H0[Nn * 256];
__device__ __align__(16) float g_H1[Nn * 256];
__device__ __align__(16) float g_F[Mm * 256];     // E1 @ W1_1
__device__ __align__(16) float g_z[Nn * 16];
__device__ __align__(16) float g_Ez[Mm * 16];
__device__ __align__(16) float g_Gz[Nn * 16];
__device__ float g_dinv[Nn];
__device__ int   g_cntE[Mm];
__device__ int   g_cntN[Nn];
__device__ int   g_rpE[Mm + 1];
__device__ int   g_rpN[Nn + 1];
__device__ int   g_curE[Mm];
__device__ int   g_curN[Nn];
__device__ int   g_colE[NNZn];
__device__ int   g_colN[NNZn];
__device__ int   g_part[64];       // scan partials: [0..15] E, [16..63] N
__device__ float g_stats[512];     // [sum 256 | sumsq 256]
__device__ __align__(16) float g_bn_s[4][256];
__device__ __align__(16) float g_bn_t[4][256];

__device__ __forceinline__ float4 bnrelu4(float4 v, float4 s, float4 t) {
    v.x = fmaxf(fmaf(v.x, s.x, t.x), 0.f);
    v.y = fmaxf(fmaf(v.y, s.y, t.y), 0.f);
    v.z = fmaxf(fmaf(v.z, s.z, t.z), 0.f);
    v.w = fmaxf(fmaf(v.w, s.w, t.w), 0.f);
    return v;
}

// pack two floats into bf16x2 hi and residual-lo words (x in low half)
__device__ __forceinline__ void split2(float x, float y, unsigned& hi, unsigned& lo) {
    __nv_bfloat16 hx = __float2bfloat16_rn(x), hy = __float2bfloat16_rn(y);
    __nv_bfloat16 lx = __float2bfloat16_rn(x - __bfloat162float(hx));
    __nv_bfloat16 ly = __float2bfloat16_rn(y - __bfloat162float(hy));
    __nv_bfloat162 h2(hx, hy), l2(lx, ly);
    hi = *(unsigned*)&h2;
    lo = *(unsigned*)&l2;
}

__device__ __forceinline__ void mma_bf16(float* c, const unsigned* a, const unsigned* b) {
    asm volatile("mma.sync.aligned.m16n8k16.row.col.f32.bf16.bf16.f32 "
                 "{%0,%1,%2,%3}, {%4,%5,%6,%7}, {%8,%9}, {%0,%1,%2,%3};"
                 : "+f"(c[0]), "+f"(c[1]), "+f"(c[2]), "+f"(c[3])
                 : "r"(a[0]), "r"(a[1]), "r"(a[2]), "r"(a[3]),
                   "r"(b[0]), "r"(b[1]));
}

// ---------------- prep ----------------
__global__ void hg_prep() {
    int i = blockIdx.x * blockDim.x + threadIdx.x;
    if (i < Mm)  g_cntE[i] = 0;
    if (i < Nn)  g_cntN[i] = 0;
    if (i < 512) g_stats[i] = 0.f;
}

__global__ void hg_count(const int* __restrict__ ei, const int* __restrict__ ni) {
    int k = blockIdx.x * blockDim.x + threadIdx.x;
    if (k >= NNZn) return;
    atomicAdd(&g_cntE[ei[k]], 1);
    atomicAdd(&g_cntN[ni[k]], 1);
}

// ---------------- multi-block two-level scan ----------------
__global__ void hg_scan1(const int* __restrict__ cnt, int* __restrict__ rp, int n, int pbase) {
    __shared__ int wsum[32];
    int i = blockIdx.x * 1024 + threadIdx.x;
    int lane = threadIdx.x & 31, wid = threadIdx.x >> 5;
    int v = (i < n) ? cnt[i] : 0;
    int x = v;
    #pragma unroll
    for (int d = 1; d < 32; d <<= 1) {
        int t = __shfl_up_sync(0xffffffffu, x, d);
        if (lane >= d) x += t;
    }
    if (lane == 31) wsum[wid] = x;
    __syncthreads();
    if (wid == 0) {
        int w = wsum[lane];
        #pragma unroll
        for (int d = 1; d < 32; d <<= 1) {
            int t = __shfl_up_sync(0xffffffffu, w, d);
            if (lane >= d) w += t;
        }
        wsum[lane] = w;
    }
    __syncthreads();
    int excl = x - v + (wid > 0 ? wsum[wid - 1] : 0);
    if (i < n) rp[i] = excl;
    if (threadIdx.x == 1023) g_part[pbase + blockIdx.x] = excl + v;
}

__global__ void hg_scan2(int nbE, int nbN) {
    if (threadIdx.x == 0) {
        int s = 0;
        for (int i = 0; i < nbE; i++) { int t = g_part[i]; g_part[i] = s; s += t; }
        g_rpE[Mm] = s;
    }
    if (threadIdx.x == 1) {
        int s = 0;
        for (int i = 16; i < 16 + nbN; i++) { int t = g_part[i]; g_part[i] = s; s += t; }
        g_rpN[Nn] = s;
    }
}

__global__ void hg_scan3(int* __restrict__ rp, int* __restrict__ cur, int n, int pbase) {
    int i = blockIdx.x * 1024 + threadIdx.x;
    if (i >= n) return;
    int v = rp[i] + g_part[pbase + (i >> 10)];
    rp[i] = v;
    cur[i] = v;
}

__global__ void hg_fill(const int* __restrict__ ei, const int* __restrict__ ni) {
    int k = blockIdx.x * blockDim.x + threadIdx.x;
    if (k >= NNZn) return;
    int e = ei[k], nd = ni[k];
    int pe = atomicAdd(&g_curE[e], 1);  g_colE[pe] = nd;
    int pn = atomicAdd(&g_curN[nd], 1); g_colN[pn] = e;
}

__global__ void hg_dinv() {
    int i = blockIdx.x * blockDim.x + threadIdx.x;
    if (i >= Nn) return;
    int s = 0;
    for (int b = g_rpN[i], e = g_rpN[i + 1]; b < e; ++b) s += g_cntE[g_colN[b]];
    g_dinv[i] = (s > 0) ? 1.f / (float)s : 1.f;
}

// ---------------- pull-based segment sum ----------------
template <int NF4>
__global__ void hg_seg_pull(const int* __restrict__ rp, const int* __restrict__ col,
                            const float4* __restrict__ src, float4* __restrict__ dst,
                            int nseg, int slot) {
    const int WPS = NF4 / 32;
    int gw  = (blockIdx.x * blockDim.x + threadIdx.x) >> 5;
    int seg = gw / WPS;
    if (seg >= nseg) return;
    int f4 = (gw % WPS) * 32 + (threadIdx.x & 31);
    float4 sv, tv;
    bool bn = (slot >= 0);
    if (bn) {
        sv = *(const float4*)&g_bn_s[slot][f4 * 4];
        tv = *(const float4*)&g_bn_t[slot][f4 * 4];
    }
    float4 acc = make_float4(0.f, 0.f, 0.f, 0.f);
    int b = rp[seg], e = rp[seg + 1];
    for (; b + 1 < e; b += 2) {
        int r0 = col[b], r1 = col[b + 1];
        float4 v0 = __ldg(&src[(size_t)r0 * NF4 + f4]);
        float4 v1 = __ldg(&src[(size_t)r1 * NF4 + f4]);
        if (bn) { v0 = bnrelu4(v0, sv, tv); v1 = bnrelu4(v1, sv, tv); }
        acc.x += v0.x + v1.x; acc.y += v0.y + v1.y;
        acc.z += v0.z + v1.z; acc.w += v0.w + v1.w;
    }
    if (b < e) {
        float4 v0 = __ldg(&src[(size_t)col[b] * NF4 + f4]);
        if (bn) v0 = bnrelu4(v0, sv, tv);
        acc.x += v0.x; acc.y += v0.y; acc.z += v0.z; acc.w += v0.w;
    }
    dst[(size_t)seg * NF4 + f4] = acc;
}

__global__ void hg_seg_pull16(const int* __restrict__ rp, const int* __restrict__ col,
                              const float* __restrict__ src, float* __restrict__ dst, int nseg) {
    int t = blockIdx.x * blockDim.x + threadIdx.x;
    int seg = t >> 4;
    if (seg >= nseg) return;
    int f = t & 15;
    float acc = 0.f;
    for (int b = rp[seg], e = rp[seg + 1]; b < e; ++b)
        acc += __ldg(&src[(size_t)col[b] * 16 + f]);
    dst[(size_t)seg * 16 + f] = acc;
}

// ---------------- tensor-core GEMM: C = act(A)[Mr,K] @ B[K,Nc] ----------------
// bf16 3-split (hi*hi + hi*lo + lo*hi) -> ~1e-5 rel err, fp32 accumulate.
// Block tile 128x128, 8 warps in 2(M)x4(N), warp tile 64x32 = 4x4 m16n8k16.
// slot>=0: BN+ReLU fused on A load. doStats: column sum/sumsq -> g_stats.
__global__ __launch_bounds__(256) void hg_gemm_tc(
        const float* __restrict__ A, const float* __restrict__ B, float* __restrict__ C,
        int Mr, int K, int Nc, int slot, int doStats) {
    __shared__ unsigned Ah[128][17], Al[128][17];
    __shared__ unsigned Bh[16][136], Bl[16][136];
    __shared__ float s_sum[128], s_sq[128];

    int tid = threadIdx.x;
    int lane = tid & 31, wid = tid >> 5;
    int wm = wid & 1, wn = wid >> 1;
    int row0 = blockIdx.y * 128, col0 = blockIdx.x * 128;

    if (doStats && tid < 128) { s_sum[tid] = 0.f; s_sq[tid] = 0.f; }

    float c[4][4][4];
    #pragma unroll
    for (int mi = 0; mi < 4; mi++)
        #pragma unroll
        for (int ni = 0; ni < 4; ni++)
            #pragma unroll
            for (int q = 0; q < 4; q++) c[mi][ni][q] = 0.f;

    int arow = tid >> 3;          // 0..31
    int acol = (tid & 7) * 4;     // 0..28
    int bk2  = tid >> 4;          // 0..15
    int bnn  = (tid & 15) * 8;    // 0..120

    for (int k0 = 0; k0 < K; k0 += 32) {
        // A tile 128x32 fp32 -> bf16 hi/lo, BN+ReLU fused
        #pragma unroll
        for (int rr = 0; rr < 128; rr += 32) {
            int r = rr + arow;
            int gr = row0 + r;
            float4 v = make_float4(0.f, 0.f, 0.f, 0.f);
            if (gr < Mr) v = __ldg((const float4*)(A + (size_t)gr * K + k0 + acol));
            if (slot >= 0) {
                float4 s4 = *(const float4*)&g_bn_s[slot][k0 + acol];
                float4 t4 = *(const float4*)&g_bn_t[slot][k0 + acol];
                v = bnrelu4(v, s4, t4);
            }
            unsigned h0, l0, h1, l1;
            split2(v.x, v.y, h0, l0);
            split2(v.z, v.w, h1, l1);
            int kc = acol >> 1;
            Ah[r][kc] = h0;  Al[r][kc] = l0;
            Ah[r][kc + 1] = h1;  Al[r][kc + 1] = l1;
        }
        // B tile 32x128: pair along k
        {
            const float* Bp = B + (size_t)(k0 + 2 * bk2) * Nc + col0 + bnn;
            float4 r0a = __ldg((const float4*)Bp);
            float4 r0b = __ldg((const float4*)(Bp + 4));
            float4 r1a = __ldg((const float4*)(Bp + Nc));
            float4 r1b = __ldg((const float4*)(Bp + Nc + 4));
            unsigned h, l;
            split2(r0a.x, r1a.x, h, l); Bh[bk2][bnn + 0] = h; Bl[bk2][bnn + 0] = l;
            split2(r0a.y, r1a.y, h, l); Bh[bk2][bnn + 1] = h; Bl[bk2][bnn + 1] = l;
            split2(r0a.z, r1a.z, h, l); Bh[bk2][bnn + 2] = h; Bl[bk2][bnn + 2] = l;
            split2(r0a.w, r1a.w, h, l); Bh[bk2][bnn + 3] = h; Bl[bk2][bnn + 3] = l;
            split2(r0b.x, r1b.x, h, l); Bh[bk2][bnn + 4] = h; Bl[bk2][bnn + 4] = l;
            split2(r0b.y, r1b.y, h, l); Bh[bk2][bnn + 5] = h; Bl[bk2][bnn + 5] = l;
            split2(r0b.z, r1b.z, h, l); Bh[bk2][bnn + 6] = h; Bl[bk2][bnn + 6] = l;
            split2(r0b.w, r1b.w, h, l); Bh[bk2][bnn + 7] = h; Bl[bk2][bnn + 7] = l;
        }
        __syncthreads();
        #pragma unroll
        for (int s = 0; s < 2; s++) {
            unsigned ah[4][4], al[4][4], bh[4][2], bl[4][2];
            int kp = s * 8 + (lane & 3);
            #pragma unroll
            for (int mi = 0; mi < 4; mi++) {
                int r = wm * 64 + mi * 16 + (lane >> 2);
                ah[mi][0] = Ah[r][kp];     ah[mi][1] = Ah[r + 8][kp];
                ah[mi][2] = Ah[r][kp + 4]; ah[mi][3] = Ah[r + 8][kp + 4];
                al[mi][0] = Al[r][kp];     al[mi][1] = Al[r + 8][kp];
                al[mi][2] = Al[r][kp + 4]; al[mi][3] = Al[r + 8][kp + 4];
            }
            #pragma unroll
            for (int ni = 0; ni < 4; ni++) {
                int n = wn * 32 + ni * 8 + (lane >> 2);
                bh[ni][0] = Bh[kp][n]; bh[ni][1] = Bh[kp + 4][n];
                bl[ni][0] = Bl[kp][n]; bl[ni][1] = Bl[kp + 4][n];
            }
            #pragma unroll
            for (int mi = 0; mi < 4; mi++)
                #pragma unroll
                for (int ni = 0; ni < 4; ni++) {
                    mma_bf16(c[mi][ni], ah[mi], bh[ni]);
                    mma_bf16(c[mi][ni], ah[mi], bl[ni]);
                    mma_bf16(c[mi][ni], al[mi], bh[ni]);
                }
        }
        __syncthreads();
    }

    // store + fused BN stats
    #pragma unroll
    for (int ni = 0; ni < 4; ni++) {
        int lc = wn * 32 + ni * 8 + (lane & 3) * 2;
        float s0 = 0.f, s1 = 0.f, q0 = 0.f, q1 = 0.f;
        #pragma unroll
        for (int mi = 0; mi < 4; mi++) {
            int r = row0 + wm * 64 + mi * 16 + (lane >> 2);
            float* cf = c[mi][ni];
            if (r < Mr) {
                *(float2*)&C[(size_t)r * Nc + col0 + lc] = make_float2(cf[0], cf[1]);
                s0 += cf[0]; q0 = fmaf(cf[0], cf[0], q0);
                s1 += cf[1]; q1 = fmaf(cf[1], cf[1], q1);
            }
            if (r + 8 < Mr) {
                *(float2*)&C[(size_t)(r + 8) * Nc + col0 + lc] = make_float2(cf[2], cf[3]);
                s0 += cf[2]; q0 = fmaf(cf[2], cf[2], q0);
                s1 += cf[3]; q1 = fmaf(cf[3], cf[3], q1);
            }
        }
        if (doStats) {
            atomicAdd(&s_sum[lc], s0);     atomicAdd(&s_sq[lc], q0);
            atomicAdd(&s_sum[lc + 1], s1); atomicAdd(&s_sq[lc + 1], q1);
        }
    }
    if (doStats) {
        __syncthreads();
        if (tid < 128) {
            atomicAdd(&g_stats[col0 + tid], s_sum[tid]);
            atomicAdd(&g_stats[256 + col0 + tid], s_sq[tid]);
        }
    }
}

// ---------------- BatchNorm stats (for pull-produced tensors) ----------------
__global__ void hg_bn_stats(const float* __restrict__ Xm, int R) {
    int f  = threadIdx.x;
    int r0 = blockIdx.x * 128;
    int r1 = min(r0 + 128, R);
    float s = 0.f, s2 = 0.f;
    for (int r = r0; r < r1; ++r) {
        float v = Xm[(size_t)r * 256 + f];
        s += v;
        s2 = fmaf(v, v, s2);
    }
    atomicAdd(&g_stats[f], s);
    atomicAdd(&g_stats[256 + f], s2);
}

__global__ void hg_bn_fin(const float* __restrict__ gamma, const float* __restrict__ beta,
                          int slot, float Rf) {
    int f = threadIdx.x;
    float m  = g_stats[f] / Rf;
    float v  = g_stats[256 + f] / Rf - m * m;
    float sc = gamma[f] * rsqrtf(v + EPSb);
    g_bn_s[slot][f] = sc;
    g_bn_t[slot][f] = beta[f] - m * sc;
    g_stats[f] = 0.f;
    g_stats[256 + f] = 0.f;
}

// ------ head: z = relu(bn1(H0))@Wh0 + relu(bn3(H1))@Wh1, padded to 16 ------
__global__ void hg_head(const float* __restrict__ W) {
    __shared__ float Ws[5120];
    for (int l = threadIdx.x; l < 5120; l += blockDim.x) Ws[l] = W[l];
    __syncthreads();
    int t  = blockIdx.x * blockDim.x + threadIdx.x;
    int r0 = t * 2;
    if (r0 >= Nn) return;
    float acc0[10], acc1[10];
    #pragma unroll
    for (int c = 0; c < 10; c++) { acc0[c] = 0.f; acc1[c] = 0.f; }
    #pragma unroll
    for (int half = 0; half < 2; half++) {
        const float4* Hs = (const float4*)(half ? g_H1 : g_H0);
        const float4* sp = (const float4*)(half ? g_bn_s[3] : g_bn_s[1]);
        const float4* tp = (const float4*)(half ? g_bn_t[3] : g_bn_t[1]);
        const float* Wp = Ws + half * 2560;
        for (int k4 = 0; k4 < 64; k4++) {
            float4 ss = sp[k4], tt = tp[k4];
            float4 x0 = __ldg(&Hs[(size_t)r0 * 64 + k4]);
            float4 x1 = __ldg(&Hs[(size_t)(r0 + 1) * 64 + k4]);
            float a0[4], a1[4];
            *(float4*)a0 = bnrelu4(x0, ss, tt);
            *(float4*)a1 = bnrelu4(x1, ss, tt);
            const float* wr = Wp + k4 * 40;
            #pragma unroll
            for (int kk = 0; kk < 4; kk++)
                #pragma unroll
                for (int c = 0; c < 10; c++) {
                    float w = wr[kk * 10 + c];
                    acc0[c] = fmaf(a0[kk], w, acc0[c]);
                    acc1[c] = fmaf(a1[kk], w, acc1[c]);
                }
        }
    }
    #pragma unroll
    for (int c = 0; c < 10; c++) {
        g_z[(size_t)r0 * 16 + c] = acc0[c];
        g_z[(size_t)(r0 + 1) * 16 + c] = acc1[c];
    }
    #pragma unroll
    for (int c = 10; c < 16; c++) {
        g_z[(size_t)r0 * 16 + c] = 0.f;
        g_z[(size_t)(r0 + 1) * 16 + c] = 0.f;
    }
}

// ---------------- per-graph mean readout ----------------
__global__ void hg_readout(const int* __restrict__ batch, const float* __restrict__ head_b,
                           float* __restrict__ dout) {
    __shared__ int s_lo, s_hi;
    __shared__ float red[256];
    int g = blockIdx.x;
    if (threadIdx.x == 0) {
        int lo = 0, hi = Nn;
        while (lo < hi) { int mid = (lo + hi) >> 1; if (batch[mid] < g) lo = mid + 1; else hi = mid; }
        s_lo = lo;
        lo = 0; hi = Nn;
        while (lo < hi) { int mid = (lo + hi) >> 1; if (batch[mid] < g + 1) lo = mid + 1; else hi = mid; }
        s_hi = lo;
    }
    __syncthreads();
    int lo = s_lo, hi = s_hi;
    float acc[10];
    #pragma unroll
    for (int c = 0; c < 10; c++) acc[c] = 0.f;
    for (int n = lo + (int)threadIdx.x; n < hi; n += 256) {
        float dv = g_dinv[n];
        #pragma unroll
        for (int c = 0; c < 10; c++) acc[c] = fmaf(dv, g_Gz[(size_t)n * 16 + c], acc[c]);
    }
    int cnt = hi - lo;
    for (int c = 0; c < 10; c++) {
        red[threadIdx.x] = acc[c];
        __syncthreads();
        for (int s = 128; s > 0; s >>= 1) {
            if ((int)threadIdx.x < s) red[threadIdx.x] += red[threadIdx.x + s];
            __syncthreads();
        }
        if (threadIdx.x == 0)
            dout[g * 10 + c] = (cnt > 0) ? red[0] / (float)cnt + head_b[c] : 0.f;
        __syncthreads();
    }
}

extern "C" void kernel_launch(void* const* d_in, const int* in_sizes, int n_in,
                              void* d_out, int out_size) {
    const float* X     = (const float*)d_in[0];
    const int*   ni    = (const int*)d_in[1];
    const int*   ei    = (const int*)d_in[2];
    const int*   batch = (const int*)d_in[3];
    const float* W1_0  = (const float*)d_in[4];
    const float* g1_0  = (const float*)d_in[6];
    const float* be1_0 = (const float*)d_in[7];
    const float* W2_0  = (const float*)d_in[8];
    const float* bng_0 = (const float*)d_in[10];
    const float* bnb_0 = (const float*)d_in[11];
    const float* W1_1  = (const float*)d_in[12];
    const float* g1_1  = (const float*)d_in[14];
    const float* be1_1 = (const float*)d_in[15];
    const float* W2_1  = (const float*)d_in[16];
    const float* bng_1 = (const float*)d_in[18];
    const float* bnb_1 = (const float*)d_in[19];
    const float* headW = (const float*)d_in[20];
    const float* headb = (const float*)d_in[21];
    float* dout = (float*)d_out;

    float *pE, *pG, *pLIN, *pH0, *pH1, *pF, *pz, *pEz, *pGz;
    int *pcntE, *pcntN, *prpE, *prpN, *pcurE, *pcurN, *pcolE, *pcolN;
    cudaGetSymbolAddress((void**)&pE,   g_E);
    cudaGetSymbolAddress((void**)&pG,   g_G);
    cudaGetSymbolAddress((void**)&pLIN, g_LIN);
    cudaGetSymbolAddress((void**)&pH0,  g_H0);
    cudaGetSymbolAddress((void**)&pH1,  g_H1);
    cudaGetSymbolAddress((void**)&pF,   g_F);
    cudaGetSymbolAddress((void**)&pz,   g_z);
    cudaGetSymbolAddress((void**)&pEz,  g_Ez);
    cudaGetSymbolAddress((void**)&pGz,  g_Gz);
    cudaGetSymbolAddress((void**)&pcntE, g_cntE);
    cudaGetSymbolAddress((void**)&pcntN, g_cntN);
    cudaGetSymbolAddress((void**)&prpE,  g_rpE);
    cudaGetSymbolAddress((void**)&prpN,  g_rpN);
    cudaGetSymbolAddress((void**)&pcurE, g_curE);
    cudaGetSymbolAddress((void**)&pcurN, g_curN);
    cudaGetSymbolAddress((void**)&pcolE, g_colE);
    cudaGetSymbolAddress((void**)&pcolN, g_colN);

    const float Rf = (float)Nn;
    const int nbE = (Mm + 1023) / 1024;    // 10
    const int nbN = (Nn + 1023) / 1024;    // 40
    dim3 gN(2, (Nn + 127) / 128);          // TC gemm grids (Nc=256)
    dim3 gM(2, (Mm + 127) / 128);
    int statsG = (Nn + 127) / 128;

    // graph structure (CSR build, atomic-free pulls afterwards)
    hg_prep<<<(Nn + 255) / 256, 256>>>();
    hg_count<<<(NNZn + 255) / 256, 256>>>(ei, ni);
    hg_scan1<<<nbE, 1024>>>(pcntE, prpE, Mm, 0);
    hg_scan1<<<nbN, 1024>>>(pcntN, prpN, Nn, 16);
    hg_scan2<<<1, 32>>>(nbE, nbN);
    hg_scan3<<<nbE, 1024>>>(prpE, pcurE, Mm, 0);
    hg_scan3<<<nbN, 1024>>>(prpN, pcurN, Nn, 16);
    hg_fill<<<(NNZn + 255) / 256, 256>>>(ei, ni);
    hg_dinv<<<(Nn + 255) / 256, 256>>>();

    // layer 0
    hg_seg_pull<32><<<(Mm * 32 + 255) / 256, 256>>>(prpE, pcolE, (const float4*)X, (float4*)pE, Mm, -1);
    hg_seg_pull<32><<<(Nn * 32 + 255) / 256, 256>>>(prpN, pcolN, (const float4*)pE, (float4*)pG, Nn, -1);
    hg_gemm_tc<<<gN, 256>>>(pG, W1_0, pLIN, Nn, 128, 256, -1, 1);
    hg_bn_fin<<<1, 256>>>(g1_0, be1_0, 0, Rf);
    hg_gemm_tc<<<gN, 256>>>(pLIN, W2_0, pH0, Nn, 256, 256, 0, 1);
    hg_bn_fin<<<1, 256>>>(bng_0, bnb_0, 1, Rf);

    // layer 1 (W1_1 folded through H: GEMM at M rows)
    hg_seg_pull<64><<<(Mm * 64 + 255) / 256, 256>>>(prpE, pcolE, (const float4*)pH0, (float4*)pE, Mm, 1);
    hg_gemm_tc<<<gM, 256>>>(pE, W1_1, pF, Mm, 256, 256, -1, 0);
    hg_seg_pull<64><<<(Nn * 64 + 255) / 256, 256>>>(prpN, pcolN, (const float4*)pF, (float4*)pLIN, Nn, -1);
    hg_bn_stats<<<statsG, 256>>>(pLIN, Nn);
    hg_bn_fin<<<1, 256>>>(g1_1, be1_1, 2, Rf);
    hg_gemm_tc<<<gN, 256>>>(pLIN, W2_1, pH1, Nn, 256, 256, 2, 1);
    hg_bn_fin<<<1, 256>>>(bng_1, bnb_1, 3, Rf);

    // head folded before final propagation, then readout
    hg_head<<<(Nn / 2 + 255) / 256, 256>>>(headW);
    hg_seg_pull16<<<(Mm * 16 + 255) / 256, 256>>>(prpE, pcolE, pz, pEz, Mm);
    hg_seg_pull16<<<(Nn * 16 + 255) / 256, 256>>>(prpN, pcolN, pEz, pGz, Nn);
    hg_readout<<<NGn, 256>>>(batch, headb, dout);
}